// round 16
// baseline (speedup 1.0000x reference)
#include <cuda_runtime.h>

#define BN 16
#define LEN 1024
#define DM 6
#define EDx 48
#define NS 32
#define NT 16        // 64-wide time tiles per sequence
#define TT 64
#define HALO 15
#define NCH 32       // scan chunks
#define CL 32        // steps per chunk
#define EPSV 1e-5f
#define L2E 1.4426950408889634f

// ---------------- scratch (device globals; no allocations) ----------------
__device__ float2 g_P0 [BN*EDx*LEN];      // layer-1 {delta, xs} per (b,e,t)
__device__ float2 g_BC0[BN*LEN*NS];       // layer-1 {B_n, C_n} per (b,t,n)
__device__ float  g_z0 [BN*EDx*LEN];      // layer-1 gate z, (b,e,t) layout
__device__ float  g_y1 [BN*EDx*LEN];      // layer-1 scan output (incl D*xs)
__device__ float2 g_half0[BN*EDx*NT*NS];  // layer-1 first-halfchunk summaries
__device__ float2 g_tile0[BN*EDx*NT*NS];  // layer-1 tile summaries {A, H}
__device__ float2 g_tile1[BN*EDx*NT*NS];  // layer-2 tile summaries
__device__ float  g_lastC [BN*NS];        // layer-2 C at t=L-1
__device__ float  g_lastxs[BN*EDx];       // layer-2 xs at t=L-1
__device__ float  g_lastz [BN*EDx];       // layer-2 z  at t=L-1
__device__ float  g_fi[BN*EDx];           // features into head
__device__ unsigned g_ctr;
__device__ unsigned g_ctrB[BN];

__device__ __forceinline__ float ex2f(float x){ float r; asm("ex2.approx.ftz.f32 %0, %1;":"=f"(r):"f"(x)); return r; }
__device__ __forceinline__ float lg2f(float x){ float r; asm("lg2.approx.ftz.f32 %0, %1;":"=f"(r):"f"(x)); return r; }
__device__ __forceinline__ float siluf(float x){ return x/(1.f+__expf(-x)); }
// softplus via 2 MUFU ops (approx err ~2^-22 rel)
__device__ __forceinline__ float softplusf(float x){
  return lg2f(1.f+ex2f(x*L2E))*(1.f/L2E);
}
__device__ __forceinline__ float warpsum(float v){
  #pragma unroll
  for(int o=16;o;o>>=1) v += __shfl_xor_sync(0xffffffffu, v, o);
  return v;
}
__device__ __forceinline__ float mergef(float a, float b, int mask){
  int hi = threadIdx.x & mask;
  float t = hi ? b : a;
  float u = hi ? a : b;
  return t + __shfl_xor_sync(0xffffffffu, u, mask);
}
// Affine compose: earlier e then later l.  h -> l.x*(e.x*h+e.y)+l.y
__device__ __forceinline__ float2 compaff(float2 e, float2 l){
  return make_float2(l.x*e.x, fmaf(l.x, e.y, l.y));
}

// ---------------- shared layout (floats) ----------------
#define S_DSUM 0      // 96:   sum(delta) per (e, halfchunk)
#define S_OW   96     // 288:  out_proj w (layer-1 path)
#define S_DLT  384    // 64:   raw dt per j
#define S_SB   448    // 2112: B, [j*33 + n]
#define S_XC   2560   // 3328: xs post-conv, [j*52 + c]  (16B-aligned rows)
#define S_POOL 5888   // 6144: phase-aliased pool (16B-aligned)
#define S_TOT  12032  // 48128 B
// pool sub-regions (phase-disjoint):
#define P_U    (S_POOL)        // 474:  u[(79)*6]
#define P_CW   (S_POOL+476)    // 768:  conv w transposed [k*48+c]
#define P_SP   (S_POOL+1244)   // 3792: pre-xs [i*48+c]; gg staging (16B-aligned)
#define P_WX   (S_POOL)        // 3380: x_proj w transposed [m*52+c]
#define P_PD   (S_POOL)        // 6144: float2 {delta, delta*xs} [e*64+j]

template<int LAYER>
__global__ void __launch_bounds__(256) k_preA(
  const float* __restrict__ x,   const float* __restrict__ Win,
  const float* __restrict__ convw, const float* __restrict__ convb,
  const float* __restrict__ Wx,  const float* __restrict__ dtw,
  const float* __restrict__ dtb, const float* __restrict__ alog,
  const float* __restrict__ nw,  const float* __restrict__ ow,
  const float* __restrict__ Dw,
  const float* __restrict__ fcw, const float* __restrict__ fcb,
  const float* __restrict__ clsw, const float* __restrict__ clsb,
  const float* __restrict__ regw, const float* __restrict__ regb,
  float* __restrict__ out)
{
  __shared__ __align__(16) float sm[S_TOT];
  __shared__ unsigned sPos;
  __shared__ int sLast;
  const int tid = threadIdx.x;
  const int b = blockIdx.x >> 4, tile = blockIdx.x & 15, t0 = tile*TT;

  // conv weights transposed [k*48+c] (conflict-free conv reads)
  for(int i=tid;i<EDx*16;i+=256){
    int c=i>>4, k=i&15;
    sm[P_CW + k*EDx + c]=convw[i];
  }
  if (LAYER==1) for(int i=tid;i<EDx*DM;i+=256) sm[S_OW+i]=ow[i];

  if (LAYER==0){
    for(int i=tid;i<TT+HALO;i+=256){
      int t=t0-HALO+i;
      if(t>=0){
        float v[DM]; float ss=0.f;
        #pragma unroll
        for(int d=0;d<DM;d++){ v[d]=x[(b*LEN+t)*DM+d]; ss=fmaf(v[d],v[d],ss); }
        float r=rsqrtf(ss*(1.f/DM)+EPSV);
        #pragma unroll
        for(int d=0;d<DM;d++) sm[P_U+i*DM+d]=v[d]*r*nw[d];
      } else {
        #pragma unroll
        for(int d=0;d<DM;d++) sm[P_U+i*DM+d]=0.f;
      }
    }
    __syncthreads();
  } else {
    // Stage A: gather gated y (coalesced; unrolled for MLP)
    #pragma unroll
    for(int r=0;r<15;r++){
      int idx=tid+r*256;
      if(idx<EDx*(TT+HALO)){
        int e=idx/(TT+HALO), i=idx-e*(TT+HALO); int t=t0-HALO+i;
        float g=0.f;
        if(t>=0){
          float yv=g_y1[(b*EDx+e)*LEN+t];
          float zv=g_z0[(b*EDx+e)*LEN+t];
          g=yv*siluf(zv);
        }
        sm[P_SP+e*(TT+HALO)+i]=g;
      }
    }
    __syncthreads();
    // Stage B phase 1: (i,d)-parallel raw h = x + g @ out_proj
    #pragma unroll
    for(int r=0;r<2;r++){
      int idx=tid+r*256;
      if(idx<(TT+HALO)*DM){
        int i=idx/DM, d=idx-i*DM; int t=t0-HALO+i;
        float a=0.f;
        if(t>=0){
          a=x[(b*LEN+t)*DM+d];
          #pragma unroll 12
          for(int e=0;e<EDx;e++) a=fmaf(sm[P_SP+e*(TT+HALO)+i], sm[S_OW+e*DM+d], a);
        }
        sm[P_U+idx]=a;
      }
    }
    __syncthreads();
    // Stage B phase 2: rmsnorm in place
    for(int i=tid;i<TT+HALO;i+=256){
      float ss=0.f;
      #pragma unroll
      for(int d=0;d<DM;d++){ float v=sm[P_U+i*DM+d]; ss=fmaf(v,v,ss); }
      float r=rsqrtf(ss*(1.f/DM)+EPSV);
      #pragma unroll
      for(int d=0;d<DM;d++) sm[P_U+i*DM+d]*= r*nw[d];
    }
    __syncthreads();
  }
  // pre-conv xs = u @ Win[:, :48]  -> P_SP[i*48+c]
  #pragma unroll
  for(int r=0;r<15;r++){
    int idx=tid+r*256;
    if(idx<(TT+HALO)*EDx){
      int i=idx/EDx, c=idx-i*EDx;
      const float* u=&sm[P_U+i*DM];
      float a=0.f;
      #pragma unroll
      for(int d=0;d<DM;d++) a=fmaf(u[d], __ldg(&Win[d*96+c]), a);
      sm[P_SP+idx]=a;
    }
  }
  // z = u @ Win[:, 48:]
  if (LAYER==0){
    #pragma unroll
    for(int r=0;r<12;r++){
      int idx=tid+r*256;
      int e=idx>>6, j=idx&63;
      const float* u=&sm[P_U+(j+HALO)*DM];
      float a=0.f;
      #pragma unroll
      for(int d=0;d<DM;d++) a=fmaf(u[d], __ldg(&Win[d*96+48+e]), a);
      g_z0[(b*EDx+e)*LEN + t0 + j]=a;
    }
  } else {
    if (tile==15 && tid<EDx){
      const float* u=&sm[P_U+78*DM];
      float a=0.f;
      #pragma unroll
      for(int d=0;d<DM;d++) a=fmaf(u[d], __ldg(&Win[d*96+48+tid]), a);
      g_lastz[b*EDx+tid]=a;
    }
  }
  __syncthreads();
  // Prefetch x_proj weights into registers (hidden under conv below)
  float wreg[13];
  #pragma unroll
  for(int r=0;r<13;r++){
    int i=tid+r*256;
    wreg[r] = (i<EDx*65)? __ldg(&Wx[i]) : 0.f;
  }
  // causal depthwise conv + bias + silu, vectorized float4 over c -> XC[j*52+c]
  {
    const float4* CW4 =(const float4*)&sm[P_CW];
    const float4* SP4 =(const float4*)&sm[P_SP];
    float4* XC4w=(float4*)&sm[S_XC];
    const float4* cb4 =(const float4*)convb;
    #pragma unroll
    for(int r=0;r<3;r++){
      int idx=tid+r*256;            // 0..767 = (j, c4)
      int j=idx/12, c4=idx%12;
      float4 a=cb4[c4];
      #pragma unroll
      for(int k=0;k<16;k++){
        float4 w=CW4[k*12+c4];
        float4 v=SP4[(j+k)*12+c4];
        a.x=fmaf(w.x,v.x,a.x); a.y=fmaf(w.y,v.y,a.y);
        a.z=fmaf(w.z,v.z,a.z); a.w=fmaf(w.w,v.w,a.w);
      }
      a.x=siluf(a.x); a.y=siluf(a.y); a.z=siluf(a.z); a.w=siluf(a.w);
      XC4w[j*13+c4]=a;
    }
  }
  __syncthreads();
  // store prefetched x_proj weights TRANSPOSED [m*52+c]
  #pragma unroll
  for(int r=0;r<13;r++){
    int i=tid+r*256;
    if(i<EDx*65){
      int c=i/65, m=i-c*65;
      sm[P_WX + m*52 + c]=wreg[r];
    }
  }
  __syncthreads();
  // x_proj: thread = (j, quarter), outputs m = q+4k; float4 over c.
  {
    int j=tid>>2, q=tid&3;
    float acc[17];
    #pragma unroll
    for(int k=0;k<17;k++) acc[k]=0.f;
    const float4* XC4=(const float4*)&sm[S_XC];
    const float4* W4 =(const float4*)&sm[P_WX];
    #pragma unroll
    for(int c4=0;c4<12;c4++){
      float4 xv=XC4[j*13+c4];
      #pragma unroll
      for(int k=0;k<17;k++){
        int m=q+4*k;
        if(m<=64){
          float4 w=W4[m*13+c4];
          acc[k]=fmaf(xv.x,w.x,fmaf(xv.y,w.y,fmaf(xv.z,w.z,fmaf(xv.w,w.w,acc[k]))));
        }
      }
    }
    int t=t0+j;
    #pragma unroll
    for(int k=0;k<17;k++){
      int m=q+4*k;
      if(m<=64){
        float a=acc[k];
        if(m==0) sm[S_DLT+j]=a;
        else if(m<=32){
          sm[S_SB+j*33+(m-1)]=a;
          if(LAYER==0) ((float*)g_BC0)[((size_t)b*LEN+t)*(2*NS) + (m-1)*2]=a;
        } else {
          if(LAYER==0) ((float*)g_BC0)[((size_t)b*LEN+t)*(2*NS) + (m-33)*2+1]=a;
          else if(tile==15 && j==63) g_lastC[b*NS+(m-33)]=a;
        }
      }
    }
  }
  __syncthreads();
  // delta = softplus(...); pack PD = {delta, delta*xs}; halfchunk delta sums
  {
    float2* PD2=(float2*)&sm[P_PD];
    #pragma unroll
    for(int r=0;r<12;r++){
      int idx=tid+r*256;
      int e=idx>>6, j=idx&63;
      float delta = softplusf(fmaf(sm[S_DLT+j], dtw[e], dtb[e]));
      float s = warpsum(delta);
      if((j&31)==0) sm[S_DSUM+e*2+(j>>5)]=s;
      float xs=sm[S_XC + j*52 + e];
      PD2[e*64+j]=make_float2(delta, delta*xs);
      if(LAYER==0)
        g_P0[(b*EDx+e)*LEN + t0 + j] = make_float2(delta, xs);
    }
  }
  if (LAYER==1 && tile==15 && tid<EDx) g_lastxs[b*EDx+tid]=sm[S_XC + 63*52 + tid];
  __syncthreads();
  // segA: warp w owns e = w+8*eo. 6 recurrences interleaved; LDS.128 = 2 steps.
  {
    int w=tid>>5, n=tid&31;
    const float4* PD4=(const float4*)&sm[P_PD];
    float H[6], Hh[6], ac[6];
    #pragma unroll
    for(int eo=0;eo<6;eo++){
      int e=w+eo*8;
      ac[eo]=-__expf(alog[e*NS+n])*L2E;
      H[eo]=0.f;
    }
    #pragma unroll 2
    for(int s2=0;s2<32;s2++){           // pair of steps (2*s2, 2*s2+1)
      int s=s2*2;
      float Bv0=sm[S_SB+s*33+n];
      float Bv1=sm[S_SB+(s+1)*33+n];
      #pragma unroll
      for(int eo=0;eo<6;eo++){
        int e=w+eo*8;
        float4 pd=PD4[e*32+s2];         // {d0, d0*xs0, d1, d1*xs1}
        H[eo]=fmaf(ex2f(pd.x*ac[eo]), H[eo], pd.y*Bv0);
        H[eo]=fmaf(ex2f(pd.z*ac[eo]), H[eo], pd.w*Bv1);
      }
      if(s2==15){
        #pragma unroll
        for(int eo=0;eo<6;eo++) Hh[eo]=H[eo];
      }
    }
    #pragma unroll
    for(int eo=0;eo<6;eo++){
      int e=w+eo*8;
      float d0=sm[S_DSUM+e*2+0], d1=sm[S_DSUM+e*2+1];
      float A0=ex2f(ac[eo]*d0);
      float At=ex2f(ac[eo]*(d0+d1));
      size_t o = ((size_t)(b*EDx+e)*NT + tile)*NS + n;
      if(LAYER==0){ g_half0[o]=make_float2(A0,Hh[eo]); g_tile0[o]=make_float2(At,H[eo]); }
      else        { g_tile1[o]=make_float2(At,H[eo]); }
    }
  }
  // ---------------- LAYER 1 epilogue: per-b combine, then head ----------------
  if (LAYER==1){
    __threadfence();
    __syncthreads();
    if(tid==0) sPos = atomicAdd(&g_ctrB[b],1u);
    __syncthreads();
    if (sPos != 15u) return;
    if(tid==0) g_ctrB[b]=0;
    __threadfence();
    {
      int w=tid>>5, n=tid&31;
      #pragma unroll
      for(int k=0;k<6;k++){
        int e=w+8*k;
        const float2* S=&g_tile1[((size_t)(b*EDx+e)*NT)*NS+n];
        float2 v[16];
        #pragma unroll
        for(int t=0;t<16;t++) v[t]=S[t*NS];      // 16 independent loads
        #pragma unroll
        for(int t=0;t<8;t++) v[t]=compaff(v[2*t], v[2*t+1]);
        #pragma unroll
        for(int t=0;t<4;t++) v[t]=compaff(v[2*t], v[2*t+1]);
        #pragma unroll
        for(int t=0;t<2;t++) v[t]=compaff(v[2*t], v[2*t+1]);
        v[0]=compaff(v[0], v[1]);
        float h=v[0].y;                          // h0 = 0
        float sv=warpsum(h * g_lastC[b*NS+n]);
        if(n==0){
          float y=fmaf(Dw[e], g_lastxs[b*EDx+e], sv);
          g_fi[b*EDx+e]=y*siluf(g_lastz[b*EDx+e]);
        }
      }
    }
    __threadfence();
    __syncthreads();
    if(tid==0) sLast = (atomicAdd(&g_ctr,1u)==(unsigned)(BN-1));
    __syncthreads();
    if(!sLast) return;
    if(tid==0) g_ctr=0;
    __threadfence();
    // head: fc -> relu -> cls / reg
    float* feat=&sm[S_POOL];
    for(int idx=tid; idx<BN*EDx; idx+=256){
      int bb=idx/EDx, j=idx-bb*EDx;
      float a=fcb[j];
      #pragma unroll 12
      for(int ee=0;ee<EDx;ee++) a=fmaf(g_fi[bb*EDx+ee], fcw[ee*EDx+j], a);
      feat[idx]=fmaxf(a,0.f);
    }
    __syncthreads();
    if(tid<BN*4){
      int bb=tid>>2,k=tid&3;
      float a=clsb[k];
      #pragma unroll 12
      for(int j=0;j<EDx;j++) a=fmaf(feat[bb*EDx+j], clsw[j*4+k], a);
      out[bb*4+k]=a;
    } else if(tid<BN*4+BN){
      int bb=tid-BN*4;
      float a=regb[0];
      #pragma unroll 12
      for(int j=0;j<EDx;j++) a=fmaf(feat[bb*EDx+j], regw[j], a);
      out[BN*4+bb]=a;
    }
  }
}

// Layer-1 replay: block = (b, chunk, e-sixth); BC + P staged in smem.
// BC restaged step-paired: sBC4[s2*32+n] = {B(2s2),C(2s2),B(2s2+1),C(2s2+1)}.
__global__ void __launch_bounds__(512) k_segC(const float* __restrict__ alog,
                                              const float* __restrict__ Dw)
{
  __shared__ __align__(16) float4 sBC4[16*NS];    // 8KB
  __shared__ __align__(16) float2 sP [16*CL];     // 4KB  [el*32+j]
  int blk=blockIdx.x;
  int eg = blk % 3;
  int c  = (blk/3) % NCH;
  int b  = blk/(3*NCH);
  int tid= threadIdx.x;
  int w=tid>>5, n=tid&31;
  int e = eg*16 + w;

  // stage BC: each thread loads 2 consecutive (t,n) float2 pairs via LDG.128
  {
    const float2* src=&g_BC0[((size_t)b*LEN + c*CL)*NS];
    float4 v=*(const float4*)(src + tid*2);
    int t=tid>>4, n0=(tid&15)*2;
    float* base=(float*)sBC4;
    int off=((t>>1)*NS+n0)*4+(t&1)*2;
    *(float2*)&base[off]   =make_float2(v.x,v.y);
    *(float2*)&base[off+4] =make_float2(v.z,v.w);
  }
  // stage P: 256 float4 items
  if(tid<256){
    int el=tid>>4, j2=tid&15;
    *(float4*)&sP[el*CL+j2*2] =
      *(const float4*)&g_P0[(b*EDx+eg*16+el)*LEN + c*CL + j2*2];
  }

  float acoef = -__expf(alog[e*NS+n])*L2E;
  // hierarchical lookback: full tiles, then one halfchunk if odd
  int T = c>>1;
  const float2* TS=&g_tile0[((size_t)(b*EDx+e)*NT)*NS + n];
  float h=0.f;
  #pragma unroll 4
  for(int tt=0;tt<T;tt++){ float2 s=TS[tt*NS]; h=fmaf(s.x,h,s.y); }
  if(c&1){ float2 s=g_half0[((size_t)(b*EDx+e)*NT+T)*NS+n]; h=fmaf(s.x,h,s.y); }
  __syncthreads();

  const float2* P = &sP[w*CL];
  const float4* P4 = (const float4*)P;            // 2 steps per load
  float acc0,acc1,acc2,acc3,acc4,res=0.f;
  #pragma unroll
  for(int j2=0;j2<16;j2++){
    float4 pq = P4[j2];
    float4 bb = sBC4[j2*NS+n];
    // even step
    float a = ex2f(pq.x*acoef);
    h = fmaf(a, h, (pq.x*pq.y)*bb.x);
    acc0 = h*bb.y;
    // odd step
    a = ex2f(pq.z*acoef);
    h = fmaf(a, h, (pq.z*pq.w)*bb.z);
    float cur = h*bb.w;
    cur=mergef(acc0,cur,1);
    if(j2&1){ cur=mergef(acc1,cur,2);
      if(j2&2){ cur=mergef(acc2,cur,4);
        if(j2&4){ cur=mergef(acc3,cur,8);
          if(j2&8){ res=mergef(acc4,cur,16); }
          else acc4=cur; }
        else acc3=cur; }
      else acc2=cur; }
    else acc1=cur;
  }
  g_y1[(b*EDx+e)*LEN + c*CL + n] = fmaf(Dw[e], P[n].y, res);
}

extern "C" void kernel_launch(void* const* d_in, const int* in_sizes, int n_in,
                              void* d_out, int out_size)
{
  const float* x    =(const float*)d_in[0];
  const float* ipw  =(const float*)d_in[1];   // (2,6,96)
  const float* cw   =(const float*)d_in[2];   // (2,48,16)
  const float* cb   =(const float*)d_in[3];   // (2,48)
  const float* xpw  =(const float*)d_in[4];   // (2,48,65)
  const float* dtw  =(const float*)d_in[5];   // (2,1,48)
  const float* dtb  =(const float*)d_in[6];   // (2,48)
  const float* alog =(const float*)d_in[7];   // (2,48,32)
  const float* Dw   =(const float*)d_in[8];   // (2,48)
  const float* nw   =(const float*)d_in[9];   // (2,6)
  const float* ow   =(const float*)d_in[10];  // (1,48,6)
  const float* fcw  =(const float*)d_in[11];
  const float* fcb  =(const float*)d_in[12];
  const float* clsw =(const float*)d_in[13];
  const float* clsb =(const float*)d_in[14];
  const float* regw =(const float*)d_in[15];
  const float* regb =(const float*)d_in[16];
  float* out = (float*)d_out;

  k_preA<0><<<BN*NT, 256>>>(x, ipw, cw, cb, xpw, dtw, dtb, alog, nw, ow,
                            Dw, fcw, fcb, clsw, clsb, regw, regb, out);
  k_segC   <<<BN*NCH*3, 512>>>(alog, Dw);
  k_preA<1><<<BN*NT, 256>>>(x, ipw+6*96, cw+768, cb+48, xpw+3120,
                            dtw+48, dtb+48, alog+1536, nw+DM, ow,
                            Dw+48, fcw, fcb, clsw, clsb, regw, regb, out);
}

// round 17
// speedup vs baseline: 1.0887x; 1.0887x over previous
#include <cuda_runtime.h>

#define BN 16
#define LEN 1024
#define DM 6
#define EDx 48
#define NS 32
#define NT 16        // 64-wide time tiles per sequence
#define TT 64
#define HALO 15
#define NCH 32       // scan chunks
#define CL 32        // steps per chunk
#define EPSV 1e-5f
#define L2E 1.4426950408889634f

// ---------------- scratch (device globals; no allocations) ----------------
__device__ float2 g_P0 [BN*EDx*LEN];      // layer-1 {delta, xs} per (b,e,t)
__device__ float2 g_BC0[BN*LEN*NS];       // layer-1 {B_n, C_n} per (b,t,n)
__device__ float  g_z0 [BN*EDx*LEN];      // layer-1 gate z, (b,e,t) layout
__device__ float  g_y1 [BN*EDx*LEN];      // layer-1 GATED scan output
__device__ float2 g_half0[BN*EDx*NT*NS];  // layer-1 first-halfchunk summaries
__device__ float2 g_tile0[BN*EDx*NT*NS];  // layer-1 tile summaries {A, H}
__device__ float2 g_tile1[BN*EDx*NT*NS];  // layer-2 tile summaries
__device__ float  g_lastC [BN*NS];        // layer-2 C at t=L-1
__device__ float  g_lastxs[BN*EDx];       // layer-2 xs at t=L-1
__device__ float  g_lastz [BN*EDx];       // layer-2 z  at t=L-1
__device__ float  g_fi[BN*EDx];           // features into head
__device__ unsigned g_ctr;
__device__ unsigned g_ctrB[BN];

__device__ __forceinline__ float ex2f(float x){ float r; asm("ex2.approx.ftz.f32 %0, %1;":"=f"(r):"f"(x)); return r; }
__device__ __forceinline__ float lg2f(float x){ float r; asm("lg2.approx.ftz.f32 %0, %1;":"=f"(r):"f"(x)); return r; }
__device__ __forceinline__ float siluf(float x){ return x/(1.f+__expf(-x)); }
// softplus via 2 MUFU ops (approx err ~2^-22 rel; validated R15/R16)
__device__ __forceinline__ float softplusf(float x){
  return lg2f(1.f+ex2f(x*L2E))*(1.f/L2E);
}
__device__ __forceinline__ float warpsum(float v){
  #pragma unroll
  for(int o=16;o;o>>=1) v += __shfl_xor_sync(0xffffffffu, v, o);
  return v;
}
__device__ __forceinline__ float mergef(float a, float b, int mask){
  int hi = threadIdx.x & mask;
  float t = hi ? b : a;
  float u = hi ? a : b;
  return t + __shfl_xor_sync(0xffffffffu, u, mask);
}
// Affine compose: earlier e then later l.  h -> l.x*(e.x*h+e.y)+l.y
__device__ __forceinline__ float2 compaff(float2 e, float2 l){
  return make_float2(l.x*e.x, fmaf(l.x, e.y, l.y));
}

// ---------------- shared layout (floats) ----------------
#define S_DSUM 0      // 96:   sum(delta) per (e, halfchunk)
#define S_OW   96     // 288:  out_proj w (layer-1 path)
#define S_DLT  384    // 64:   raw dt per j
#define S_SB   448    // 2112: B, [j*33 + n]
#define S_XC   2560   // 3328: xs post-conv, [j*52 + c]  (16B-aligned rows)
#define S_POOL 5888   // 6144: phase-aliased pool (16B-aligned)
#define S_TOT  12032  // 48128 B
// pool sub-regions (phase-disjoint):
#define P_U    (S_POOL)        // 474:  u[(79)*6]
#define P_CW   (S_POOL+476)    // 768:  conv w transposed [k*48+c]
#define P_SP   (S_POOL+1244)   // 3792: pre-xs [i*48+c]; gg staging (16B-aligned)
#define P_WX   (S_POOL)        // 3380: x_proj w transposed [m*52+c]
#define P_PD   (S_POOL)        // 6144: float2 {delta, delta*xs} [e*64+j]

template<int LAYER>
__global__ void __launch_bounds__(256) k_preA(
  const float* __restrict__ x,   const float* __restrict__ Win,
  const float* __restrict__ convw, const float* __restrict__ convb,
  const float* __restrict__ Wx,  const float* __restrict__ dtw,
  const float* __restrict__ dtb, const float* __restrict__ alog,
  const float* __restrict__ nw,  const float* __restrict__ ow,
  const float* __restrict__ Dw,
  const float* __restrict__ fcw, const float* __restrict__ fcb,
  const float* __restrict__ clsw, const float* __restrict__ clsb,
  const float* __restrict__ regw, const float* __restrict__ regb,
  float* __restrict__ out)
{
  __shared__ __align__(16) float sm[S_TOT];
  __shared__ unsigned sPos;
  __shared__ int sLast;
  const int tid = threadIdx.x;
  const int b = blockIdx.x >> 4, tile = blockIdx.x & 15, t0 = tile*TT;

  // conv weights transposed [k*48+c] (conflict-free conv reads)
  for(int i=tid;i<EDx*16;i+=256){
    int c=i>>4, k=i&15;
    sm[P_CW + k*EDx + c]=convw[i];
  }
  if (LAYER==1) for(int i=tid;i<EDx*DM;i+=256) sm[S_OW+i]=ow[i];

  if (LAYER==0){
    for(int i=tid;i<TT+HALO;i+=256){
      int t=t0-HALO+i;
      if(t>=0){
        float v[DM]; float ss=0.f;
        #pragma unroll
        for(int d=0;d<DM;d++){ v[d]=x[(b*LEN+t)*DM+d]; ss=fmaf(v[d],v[d],ss); }
        float r=rsqrtf(ss*(1.f/DM)+EPSV);
        #pragma unroll
        for(int d=0;d<DM;d++) sm[P_U+i*DM+d]=v[d]*r*nw[d];
      } else {
        #pragma unroll
        for(int d=0;d<DM;d++) sm[P_U+i*DM+d]=0.f;
      }
    }
    __syncthreads();
  } else {
    // Stage A: gather pre-gated y (single stream; gating done in k_segC)
    #pragma unroll
    for(int r=0;r<15;r++){
      int idx=tid+r*256;
      if(idx<EDx*(TT+HALO)){
        int e=idx/(TT+HALO), i=idx-e*(TT+HALO); int t=t0-HALO+i;
        float g = (t>=0)? g_y1[(b*EDx+e)*LEN+t] : 0.f;
        sm[P_SP+e*(TT+HALO)+i]=g;
      }
    }
    __syncthreads();
    // Stage B phase 1: (i,d)-parallel raw h = x + g @ out_proj
    #pragma unroll
    for(int r=0;r<2;r++){
      int idx=tid+r*256;
      if(idx<(TT+HALO)*DM){
        int i=idx/DM, d=idx-i*DM; int t=t0-HALO+i;
        float a=0.f;
        if(t>=0){
          a=x[(b*LEN+t)*DM+d];
          #pragma unroll 12
          for(int e=0;e<EDx;e++) a=fmaf(sm[P_SP+e*(TT+HALO)+i], sm[S_OW+e*DM+d], a);
        }
        sm[P_U+idx]=a;
      }
    }
    __syncthreads();
    // Stage B phase 2: rmsnorm in place
    for(int i=tid;i<TT+HALO;i+=256){
      float ss=0.f;
      #pragma unroll
      for(int d=0;d<DM;d++){ float v=sm[P_U+i*DM+d]; ss=fmaf(v,v,ss); }
      float r=rsqrtf(ss*(1.f/DM)+EPSV);
      #pragma unroll
      for(int d=0;d<DM;d++) sm[P_U+i*DM+d]*= r*nw[d];
    }
    __syncthreads();
  }
  // pre-conv xs = u @ Win[:, :48]  -> P_SP[i*48+c]
  #pragma unroll
  for(int r=0;r<15;r++){
    int idx=tid+r*256;
    if(idx<(TT+HALO)*EDx){
      int i=idx/EDx, c=idx-i*EDx;
      const float* u=&sm[P_U+i*DM];
      float a=0.f;
      #pragma unroll
      for(int d=0;d<DM;d++) a=fmaf(u[d], __ldg(&Win[d*96+c]), a);
      sm[P_SP+idx]=a;
    }
  }
  // z = u @ Win[:, 48:]
  if (LAYER==0){
    #pragma unroll
    for(int r=0;r<12;r++){
      int idx=tid+r*256;
      int e=idx>>6, j=idx&63;
      const float* u=&sm[P_U+(j+HALO)*DM];
      float a=0.f;
      #pragma unroll
      for(int d=0;d<DM;d++) a=fmaf(u[d], __ldg(&Win[d*96+48+e]), a);
      g_z0[(b*EDx+e)*LEN + t0 + j]=a;
    }
  } else {
    if (tile==15 && tid<EDx){
      const float* u=&sm[P_U+78*DM];
      float a=0.f;
      #pragma unroll
      for(int d=0;d<DM;d++) a=fmaf(u[d], __ldg(&Win[d*96+48+tid]), a);
      g_lastz[b*EDx+tid]=a;
    }
  }
  __syncthreads();
  // Prefetch x_proj weights into registers (hidden under conv below)
  float wreg[13];
  #pragma unroll
  for(int r=0;r<13;r++){
    int i=tid+r*256;
    wreg[r] = (i<EDx*65)? __ldg(&Wx[i]) : 0.f;
  }
  // causal depthwise conv + bias + silu, vectorized float4 over c -> XC[j*52+c]
  {
    const float4* CW4 =(const float4*)&sm[P_CW];
    const float4* SP4 =(const float4*)&sm[P_SP];
    float4* XC4w=(float4*)&sm[S_XC];
    const float4* cb4 =(const float4*)convb;
    #pragma unroll
    for(int r=0;r<3;r++){
      int idx=tid+r*256;            // 0..767 = (j, c4)
      int j=idx/12, c4=idx%12;
      float4 a=cb4[c4];
      #pragma unroll
      for(int k=0;k<16;k++){
        float4 w=CW4[k*12+c4];
        float4 v=SP4[(j+k)*12+c4];
        a.x=fmaf(w.x,v.x,a.x); a.y=fmaf(w.y,v.y,a.y);
        a.z=fmaf(w.z,v.z,a.z); a.w=fmaf(w.w,v.w,a.w);
      }
      a.x=siluf(a.x); a.y=siluf(a.y); a.z=siluf(a.z); a.w=siluf(a.w);
      XC4w[j*13+c4]=a;
    }
  }
  __syncthreads();
  // store prefetched x_proj weights TRANSPOSED [m*52+c]
  #pragma unroll
  for(int r=0;r<13;r++){
    int i=tid+r*256;
    if(i<EDx*65){
      int c=i/65, m=i-c*65;
      sm[P_WX + m*52 + c]=wreg[r];
    }
  }
  __syncthreads();
  // x_proj: thread = (j, quarter), outputs m = q+4k; float4 over c.
  {
    int j=tid>>2, q=tid&3;
    float acc[17];
    #pragma unroll
    for(int k=0;k<17;k++) acc[k]=0.f;
    const float4* XC4=(const float4*)&sm[S_XC];
    const float4* W4 =(const float4*)&sm[P_WX];
    #pragma unroll
    for(int c4=0;c4<12;c4++){
      float4 xv=XC4[j*13+c4];
      #pragma unroll
      for(int k=0;k<17;k++){
        int m=q+4*k;
        if(m<=64){
          float4 w=W4[m*13+c4];
          acc[k]=fmaf(xv.x,w.x,fmaf(xv.y,w.y,fmaf(xv.z,w.z,fmaf(xv.w,w.w,acc[k]))));
        }
      }
    }
    int t=t0+j;
    #pragma unroll
    for(int k=0;k<17;k++){
      int m=q+4*k;
      if(m<=64){
        float a=acc[k];
        if(m==0) sm[S_DLT+j]=a;
        else if(m<=32){
          sm[S_SB+j*33+(m-1)]=a;
          if(LAYER==0) ((float*)g_BC0)[((size_t)b*LEN+t)*(2*NS) + (m-1)*2]=a;
        } else {
          if(LAYER==0) ((float*)g_BC0)[((size_t)b*LEN+t)*(2*NS) + (m-33)*2+1]=a;
          else if(tile==15 && j==63) g_lastC[b*NS+(m-33)]=a;
        }
      }
    }
  }
  __syncthreads();
  // delta = softplus(...); pack PD = {delta, delta*xs}; halfchunk delta sums
  {
    float2* PD2=(float2*)&sm[P_PD];
    #pragma unroll
    for(int r=0;r<12;r++){
      int idx=tid+r*256;
      int e=idx>>6, j=idx&63;
      float delta = softplusf(fmaf(sm[S_DLT+j], dtw[e], dtb[e]));
      float s = warpsum(delta);
      if((j&31)==0) sm[S_DSUM+e*2+(j>>5)]=s;
      float xs=sm[S_XC + j*52 + e];
      PD2[e*64+j]=make_float2(delta, delta*xs);
      if(LAYER==0)
        g_P0[(b*EDx+e)*LEN + t0 + j] = make_float2(delta, xs);
    }
  }
  if (LAYER==1 && tile==15 && tid<EDx) g_lastxs[b*EDx+tid]=sm[S_XC + 63*52 + tid];
  __syncthreads();
  // segA: warp w owns e = w+8*eo. 6 recurrences interleaved; LDS.128 = 2 steps.
  {
    int w=tid>>5, n=tid&31;
    const float4* PD4=(const float4*)&sm[P_PD];
    float H[6], Hh[6], ac[6];
    #pragma unroll
    for(int eo=0;eo<6;eo++){
      int e=w+eo*8;
      ac[eo]=-__expf(alog[e*NS+n])*L2E;
      H[eo]=0.f;
    }
    #pragma unroll 2
    for(int s2=0;s2<32;s2++){           // pair of steps (2*s2, 2*s2+1)
      int s=s2*2;
      float Bv0=sm[S_SB+s*33+n];
      float Bv1=sm[S_SB+(s+1)*33+n];
      #pragma unroll
      for(int eo=0;eo<6;eo++){
        int e=w+eo*8;
        float4 pd=PD4[e*32+s2];         // {d0, d0*xs0, d1, d1*xs1}
        H[eo]=fmaf(ex2f(pd.x*ac[eo]), H[eo], pd.y*Bv0);
        H[eo]=fmaf(ex2f(pd.z*ac[eo]), H[eo], pd.w*Bv1);
      }
      if(s2==15){
        #pragma unroll
        for(int eo=0;eo<6;eo++) Hh[eo]=H[eo];
      }
    }
    #pragma unroll
    for(int eo=0;eo<6;eo++){
      int e=w+eo*8;
      float d0=sm[S_DSUM+e*2+0], d1=sm[S_DSUM+e*2+1];
      float A0=ex2f(ac[eo]*d0);
      float At=ex2f(ac[eo]*(d0+d1));
      size_t o = ((size_t)(b*EDx+e)*NT + tile)*NS + n;
      if(LAYER==0){ g_half0[o]=make_float2(A0,Hh[eo]); g_tile0[o]=make_float2(At,H[eo]); }
      else        { g_tile1[o]=make_float2(At,H[eo]); }
    }
  }
  // ---------------- LAYER 1 epilogue: per-b combine, then head ----------------
  if (LAYER==1){
    __threadfence();
    __syncthreads();
    if(tid==0) sPos = atomicAdd(&g_ctrB[b],1u);
    __syncthreads();
    if (sPos != 15u) return;
    if(tid==0) g_ctrB[b]=0;
    __threadfence();
    {
      int w=tid>>5, n=tid&31;
      #pragma unroll
      for(int k=0;k<6;k++){
        int e=w+8*k;
        const float2* S=&g_tile1[((size_t)(b*EDx+e)*NT)*NS+n];
        float2 v[16];
        #pragma unroll
        for(int t=0;t<16;t++) v[t]=S[t*NS];      // 16 independent loads
        #pragma unroll
        for(int t=0;t<8;t++) v[t]=compaff(v[2*t], v[2*t+1]);
        #pragma unroll
        for(int t=0;t<4;t++) v[t]=compaff(v[2*t], v[2*t+1]);
        #pragma unroll
        for(int t=0;t<2;t++) v[t]=compaff(v[2*t], v[2*t+1]);
        v[0]=compaff(v[0], v[1]);
        float h=v[0].y;                          // h0 = 0
        float sv=warpsum(h * g_lastC[b*NS+n]);
        if(n==0){
          float y=fmaf(Dw[e], g_lastxs[b*EDx+e], sv);
          g_fi[b*EDx+e]=y*siluf(g_lastz[b*EDx+e]);
        }
      }
    }
    __threadfence();
    __syncthreads();
    if(tid==0) sLast = (atomicAdd(&g_ctr,1u)==(unsigned)(BN-1));
    __syncthreads();
    if(!sLast) return;
    if(tid==0) g_ctr=0;
    __threadfence();
    // head: fc -> relu -> cls / reg
    float* feat=&sm[S_POOL];
    for(int idx=tid; idx<BN*EDx; idx+=256){
      int bb=idx/EDx, j=idx-bb*EDx;
      float a=fcb[j];
      #pragma unroll 12
      for(int ee=0;ee<EDx;ee++) a=fmaf(g_fi[bb*EDx+ee], fcw[ee*EDx+j], a);
      feat[idx]=fmaxf(a,0.f);
    }
    __syncthreads();
    if(tid<BN*4){
      int bb=tid>>2,k=tid&3;
      float a=clsb[k];
      #pragma unroll 12
      for(int j=0;j<EDx;j++) a=fmaf(feat[bb*EDx+j], clsw[j*4+k], a);
      out[bb*4+k]=a;
    } else if(tid<BN*4+BN){
      int bb=tid-BN*4;
      float a=regb[0];
      #pragma unroll 12
      for(int j=0;j<EDx;j++) a=fmaf(feat[bb*EDx+j], regw[j], a);
      out[BN*4+bb]=a;
    }
  }
}

// Layer-1 replay: block = (b, chunk, e-sixth); BC + P staged in smem.
// Epilogue fuses the silu(z) gate: g_y1 stores the GATED output.
__global__ void __launch_bounds__(512) k_segC(const float* __restrict__ alog,
                                              const float* __restrict__ Dw)
{
  __shared__ __align__(16) float2 sBC[CL*NS];     // 8KB  [j*32+n]
  __shared__ __align__(16) float2 sP [16*CL];     // 4KB  [el*32+j]
  int blk=blockIdx.x;
  int eg = blk % 3;
  int c  = (blk/3) % NCH;
  int b  = blk/(3*NCH);
  int tid= threadIdx.x;
  int w=tid>>5, n=tid&31;
  int e = eg*16 + w;

  for(int idx=tid; idx<CL*NS; idx+=512)
    sBC[idx]=g_BC0[((size_t)b*LEN + c*CL + (idx>>5))*NS + (idx&31)];
  for(int idx=tid; idx<16*CL; idx+=512)
    sP[idx]=g_P0[(b*EDx + eg*16 + (idx>>5))*LEN + c*CL + (idx&31)];

  float acoef = -__expf(alog[e*NS+n])*L2E;
  float zv = g_z0[(b*EDx+e)*LEN + c*CL + n];      // early, hides under staging
  // hierarchical lookback: full tiles, then one halfchunk if odd
  int T = c>>1;
  const float2* TS=&g_tile0[((size_t)(b*EDx+e)*NT)*NS + n];
  float h=0.f;
  #pragma unroll 4
  for(int tt=0;tt<T;tt++){ float2 s=TS[tt*NS]; h=fmaf(s.x,h,s.y); }
  if(c&1){ float2 s=g_half0[((size_t)(b*EDx+e)*NT+T)*NS+n]; h=fmaf(s.x,h,s.y); }
  __syncthreads();

  const float2* P = &sP[w*CL];
  const float4* P4 = (const float4*)P;            // 2 steps per load
  float acc0,acc1,acc2,acc3,acc4,res=0.f;
  float4 pq;
  #pragma unroll
  for(int j=0;j<CL;j++){
    if((j&1)==0) pq = P4[j>>1];
    float px = (j&1)? pq.z : pq.x;
    float py = (j&1)? pq.w : pq.y;
    float2 bc = sBC[j*NS+n];
    float a = ex2f(px*acoef);
    h = fmaf(a, h, (px*py)*bc.x);
    float cur = h*bc.y;
    if (j&1){ cur=mergef(acc0,cur,1);
      if(j&2){ cur=mergef(acc1,cur,2);
        if(j&4){ cur=mergef(acc2,cur,4);
          if(j&8){ cur=mergef(acc3,cur,8);
            if(j&16){ res=mergef(acc4,cur,16); }
            else acc4=cur; }
          else acc3=cur; }
        else acc2=cur; }
      else acc1=cur; }
    else acc0=cur;
  }
  float yfull = fmaf(Dw[e], P[n].y, res);
  g_y1[(b*EDx+e)*LEN + c*CL + n] = yfull * siluf(zv);
}

extern "C" void kernel_launch(void* const* d_in, const int* in_sizes, int n_in,
                              void* d_out, int out_size)
{
  const float* x    =(const float*)d_in[0];
  const float* ipw  =(const float*)d_in[1];   // (2,6,96)
  const float* cw   =(const float*)d_in[2];   // (2,48,16)
  const float* cb   =(const float*)d_in[3];   // (2,48)
  const float* xpw  =(const float*)d_in[4];   // (2,48,65)
  const float* dtw  =(const float*)d_in[5];   // (2,1,48)
  const float* dtb  =(const float*)d_in[6];   // (2,48)
  const float* alog =(const float*)d_in[7];   // (2,48,32)
  const float* Dw   =(const float*)d_in[8];   // (2,48)
  const float* nw   =(const float*)d_in[9];   // (2,6)
  const float* ow   =(const float*)d_in[10];  // (1,48,6)
  const float* fcw  =(const float*)d_in[11];
  const float* fcb  =(const float*)d_in[12];
  const float* clsw =(const float*)d_in[13];
  const float* clsb =(const float*)d_in[14];
  const float* regw =(const float*)d_in[15];
  const float* regb =(const float*)d_in[16];
  float* out = (float*)d_out;

  k_preA<0><<<BN*NT, 256>>>(x, ipw, cw, cb, xpw, dtw, dtb, alog, nw, ow,
                            Dw, fcw, fcb, clsw, clsb, regw, regb, out);
  k_segC   <<<BN*NCH*3, 512>>>(alog, Dw);
  k_preA<1><<<BN*NT, 256>>>(x, ipw+6*96, cw+768, cb+48, xpw+3120,
                            dtw+48, dtb+48, alog+1536, nw+DM, ow,
                            Dw+48, fcw, fcb, clsw, clsb, regw, regb, out);
}